// round 2
// baseline (speedup 1.0000x reference)
#include <cuda_runtime.h>
#include <cstdint>

// Problem constants
#define B      64
#define N_SV   63
#define HID    512
#define NEW_W  28
#define NEW_H  28
#define NCELL  (NEW_W * NEW_H)   // 784
#define HT     8                 // h-channels per block
#define NTHREADS 256

// ---------------------------------------------------------------------------
// Single fused kernel (gather formulation, no atomics on global, no fill pass):
//   grid = (B, HID/HT); block = 256 threads.
//   Stage 1: build per-cell agent bitmask (uint64, N_SV=63 fits) in smem.
//   Stage 2: stage enc[b, 0..62, h0..h0+HT) into smem (2 KB).
//   Stage 3: thread t (<196) computes cells [4t, 4t+4) for each h in the
//            tile: val = max over agents in cell of enc (>=0 via 0-init),
//            then ONE coalesced float4 store. Every output element is
//            written exactly once.
// ---------------------------------------------------------------------------
__global__ __launch_bounds__(NTHREADS)
void fused_raster_kernel(const float* __restrict__ pos,     // (B, N_SV, 3)
                         const float* __restrict__ enc,     // (B, N_SV, HID)
                         const int*   __restrict__ lengths, // (B,)
                         float* __restrict__ out)           // (B, HID, 28, 28)
{
    const int b  = blockIdx.x;
    const int h0 = blockIdx.y * HT;
    const int tid = threadIdx.x;

    __shared__ unsigned long long cellMask[NCELL];     // 6272 B
    __shared__ float sEnc[N_SV][HT];                   // 2016 B

    // --- Stage 1a: zero the masks ---
    #pragma unroll
    for (int i = tid; i < NCELL; i += NTHREADS)
        cellMask[i] = 0ull;

    // --- Stage 2 (overlap-friendly): stage encodings for this h-tile ---
    // 63 agents * HT floats = 504 loads; 8 contiguous floats per agent row.
    const float* encB = enc + (size_t)b * N_SV * HID;
    for (int i = tid; i < N_SV * HT; i += NTHREADS) {
        int a  = i / HT;
        int hh = i - a * HT;
        sEnc[a][hh] = encB[a * HID + h0 + hh];
    }
    __syncthreads();

    // --- Stage 1b: each of the first 63 threads registers its agent ---
    const int len = lengths[b];
    if (tid < N_SV && tid < len) {
        const float x = pos[(b * N_SV + tid) * 3 + 0];
        const float y = pos[(b * N_SV + tid) * 3 + 1];
        int xI = (int)(x * 0.125f);   // trunc toward zero; 28/224 = 1/8 exact
        int yI = (int)(y * 0.125f);
        if (xI < NEW_W && yI < NEW_H) {
            if (xI < 0) xI = 0;
            if (yI < 0) yI = 0;
            atomicOr(&cellMask[xI * NEW_H + yI], 1ull << tid);
        }
    }
    __syncthreads();

    // --- Stage 3: compute + store. 196 threads x 4 cells = 784 cells ---
    if (tid < NCELL / 4) {
        const int c0 = tid * 4;
        const unsigned long long m0 = cellMask[c0 + 0];
        const unsigned long long m1 = cellMask[c0 + 1];
        const unsigned long long m2 = cellMask[c0 + 2];
        const unsigned long long m3 = cellMask[c0 + 3];

        float* outB = out + ((size_t)b * HID + h0) * NCELL + c0;

        #pragma unroll
        for (int hh = 0; hh < HT; hh++) {
            float4 v = make_float4(0.f, 0.f, 0.f, 0.f);
            unsigned long long m;
            m = m0; while (m) { int a = __ffsll(m) - 1; m &= m - 1; v.x = fmaxf(v.x, sEnc[a][hh]); }
            m = m1; while (m) { int a = __ffsll(m) - 1; m &= m - 1; v.y = fmaxf(v.y, sEnc[a][hh]); }
            m = m2; while (m) { int a = __ffsll(m) - 1; m &= m - 1; v.z = fmaxf(v.z, sEnc[a][hh]); }
            m = m3; while (m) { int a = __ffsll(m) - 1; m &= m - 1; v.w = fmaxf(v.w, sEnc[a][hh]); }
            *(float4*)(outB + (size_t)hh * NCELL) = v;
        }
    }
}

extern "C" void kernel_launch(void* const* d_in, const int* in_sizes, int n_in,
                              void* d_out, int out_size) {
    const float* pos     = (const float*)d_in[0];   // (B, N_SV, 3)
    const float* enc     = (const float*)d_in[1];   // (B, N_SV, HID)
    const int*   lengths = (const int*)d_in[2];     // (B,)

    dim3 grid(B, HID / HT);          // (64, 64) = 4096 blocks
    fused_raster_kernel<<<grid, NTHREADS>>>(pos, enc, lengths, (float*)d_out);
}

// round 3
// speedup vs baseline: 1.3588x; 1.3588x over previous
#include <cuda_runtime.h>
#include <cstdint>

// Problem constants
#define B        64
#define N_SV     63
#define HID      512
#define NEW_W    28
#define NEW_H    28
#define NCELL    (NEW_W * NEW_H)     // 784
#define HT       8                   // h-channels per block
#define NTHREADS 256
#define TILE_F   (HT * NCELL)        // 6272 floats per smem tile
#define TILE_F4  (TILE_F / 4)        // 1568 float4

// ---------------------------------------------------------------------------
// Single fused kernel: per (b, h-tile) block,
//   1) zero a 25KB smem grid tile (float4 stores)
//   2) scatter-max the <=63 valid agents into the smem tile
//      (<=504 smem atomics; values <=0 skipped since grid init is 0)
//   3) stream the tile to global: pure LDS.128 -> STG.128, no per-element ALU
// Every output element is written to global exactly once, no global atomics.
// ---------------------------------------------------------------------------
__global__ __launch_bounds__(NTHREADS)
void fused_raster_kernel(const float* __restrict__ pos,     // (B, N_SV, 3)
                         const float* __restrict__ enc,     // (B, N_SV, HID)
                         const int*   __restrict__ lengths, // (B,)
                         float* __restrict__ out)           // (B, HID, 28, 28)
{
    const int b   = blockIdx.x;
    const int h0  = blockIdx.y * HT;
    const int tid = threadIdx.x;

    __shared__ float sGrid[TILE_F];   // [HT][NCELL], 25088 B
    __shared__ int   sCell[N_SV];     // cell index per agent, -1 if invalid

    // --- Stage 0: agent validity + cell (63 threads) ---
    if (tid < N_SV) {
        int cell = -1;
        // lengths[b] read per-thread; L1-resident, fine
        if (tid < lengths[b]) {
            const float x = pos[(b * N_SV + tid) * 3 + 0];
            const float y = pos[(b * N_SV + tid) * 3 + 1];
            int xI = (int)(x * 0.125f);   // 28/224 = 1/8 exact; trunc toward 0
            int yI = (int)(y * 0.125f);
            if (xI < NEW_W && yI < NEW_H) {
                if (xI < 0) xI = 0;
                if (yI < 0) yI = 0;
                cell = xI * NEW_H + yI;
            }
        }
        sCell[tid] = cell;
    }

    // --- Stage 1: zero the smem tile ---
    float4* sG4 = (float4*)sGrid;
    const float4 z = make_float4(0.f, 0.f, 0.f, 0.f);
    #pragma unroll
    for (int k = 0; k < TILE_F4 / NTHREADS + 1; k++) {
        int j = tid + k * NTHREADS;
        if (j < TILE_F4) sG4[j] = z;
    }
    __syncthreads();

    // --- Stage 2: scatter-max agents into smem ---
    // 63 agents x HT channels = 504 (a, hh) pairs
    const float* encB = enc + (size_t)b * N_SV * HID + h0;
    for (int i = tid; i < N_SV * HT; i += NTHREADS) {
        const int a  = i >> 3;          // i / HT
        const int hh = i & (HT - 1);    // i % HT
        const int cell = sCell[a];
        if (cell >= 0) {
            const float v = encB[a * HID + hh];
            if (v > 0.f) {
                // all values involved are >= 0: int-compare == float-compare
                atomicMax((int*)&sGrid[hh * NCELL + cell], __float_as_int(v));
            }
        }
    }
    __syncthreads();

    // --- Stage 3: stream tile to global, write-once, fully coalesced ---
    float4* outB4 = (float4*)(out + ((size_t)b * HID + h0) * NCELL);
    #pragma unroll
    for (int k = 0; k < TILE_F4 / NTHREADS + 1; k++) {
        int j = tid + k * NTHREADS;
        if (j < TILE_F4) outB4[j] = sG4[j];
    }
}

extern "C" void kernel_launch(void* const* d_in, const int* in_sizes, int n_in,
                              void* d_out, int out_size) {
    const float* pos     = (const float*)d_in[0];   // (B, N_SV, 3)
    const float* enc     = (const float*)d_in[1];   // (B, N_SV, HID)
    const int*   lengths = (const int*)d_in[2];     // (B,)

    dim3 grid(B, HID / HT);            // (64, 64) = 4096 blocks
    fused_raster_kernel<<<grid, NTHREADS>>>(pos, enc, lengths, (float*)d_out);
}